// round 14
// baseline (speedup 1.0000x reference)
#include <cuda_runtime.h>
#include <math.h>
#include <stdint.h>

#define VOL (128*128*128)

// Accumulators (double): 0 reg_sumsq | 1-3 pair0 cross/gg/pp | 4-6 pair1 | 7-8 tv0 prod/sum | 9-10 tv1
// Zero at load; last-finishing block emits result and re-zeroes for next replay.
__device__ double g_acc[12];
__device__ unsigned g_ticket;

__device__ __forceinline__ float warp_sum(float v) {
    #pragma unroll
    for (int o = 16; o > 0; o >>= 1) v += __shfl_xor_sync(0xffffffffu, v, o);
    return v;
}

__device__ __forceinline__ void cp8(uint32_t dst, const void* src, int bytes) {
    asm volatile("cp.async.ca.shared.global [%0], [%1], 8, %2;"
                 :: "r"(dst), "l"(src), "r"(bytes));
}
#define CP_COMMIT() asm volatile("cp.async.commit_group;")
#define CP_WAIT0()  asm volatile("cp.async.wait_group 0;")

// ---------------------------------------------------------------------------
// LCC geometry: tile 64(x) x 8(y) x 32(z), halo 2. gt/pred packed in SMEM as
// float4 {g0,g1,p0,p1} per x-float2. TWO z-slices per barrier: one iteration
// does x-pass for slices (2i,2i+1), cp.async-stages slices (2i+2,2i+3), ONE
// __syncthreads, then y-pass + combine for both. 19 barriers instead of 37.
// Centers via __ldg (L2 hit). z-window in a float4 register ring.
// ---------------------------------------------------------------------------
#define TY 8
#define HX4 34            // raw row width in packed float4 (x-float2 cols)
#define HY 12
#define RAW_E (HY * HX4)  // 408 packed float4 per slice
#define RAW_S 408         // float4 per raw slice
#define XS_S  384         // float4 per xs slice (12*32)
#define RAW4(buf, sl) (((buf) * 2 + (sl)) * RAW_S)
#define XS4(buf, sl)  (4 * RAW_S + ((buf) * 2 + (sl)) * XS_S)
#define SMEM_F4 (4 * RAW_S + 4 * XS_S)       // 3168 float4
#define SMEM_BYTES (SMEM_F4 * 16)            // 50688 B

#define LCC_BLOCKS 512
#define REG_BLOCKS 512
#define TV_BLOCKS  256
#define TOTAL_BLOCKS (LCC_BLOCKS + REG_BLOCKS + TV_BLOCKS)

__global__ __launch_bounds__(256, 4) void fused_kernel(
    const float* __restrict__ F0, const float* __restrict__ F0g,
    const float* __restrict__ I0, const float* __restrict__ I0R,
    const float* __restrict__ I1, const float* __restrict__ I1R,
    const float* __restrict__ S0, const float* __restrict__ S0g,
    const float* __restrict__ S1, const float* __restrict__ S1g,
    float* __restrict__ out) {

    extern __shared__ float4 S4[];

    int blkid = blockIdx.x;
    int tid = threadIdx.x;

    if (blkid < LCC_BLOCKS) {
        // ================= LCC =================
        int blk = blkid;
        int x2_0 = (blk & 1) * 32;            // tile x origin in float2 units
        int y0 = ((blk >> 1) & 15) * TY;
        int z0 = ((blk >> 5) & 3) * 32;
        int batch = (blk >> 7) & 1;
        int pair = blk >> 8;

        const float2* gt = (const float2*)((pair == 0 ? I0 : I1) + (size_t)batch * VOL);
        const float2* pr = (const float2*)((pair == 0 ? I0R : I1R) + (size_t)batch * VOL);

        int lx = tid & 31, ly = tid >> 5;

        // ---- load roles (packed elements, 408 per slice)
        int e0 = tid, e1 = tid + 256;
        int r0 = e0 / HX4, c0 = e0 - r0 * HX4;
        int r1 = e1 / HX4, c1 = e1 - r1 * HX4;
        int gxa = x2_0 - 1 + c0, gya = y0 + r0 - 2;
        int gxb = x2_0 - 1 + c1, gyb = y0 + r1 - 2;
        bool hasE1 = (e1 < RAW_E);            // tid < 152
        bool va = ((unsigned)gxa < 64u) & ((unsigned)gya < 128u);
        bool vb = hasE1 & ((unsigned)gxb < 64u) & ((unsigned)gyb < 128u);
        int zbase = z0 - 2;
        const float2* pga = gt + (va ? (gya * 64 + gxa) : 0);
        const float2* ppa = pr + (va ? (gya * 64 + gxa) : 0);
        const float2* pgb = gt + (vb ? (gyb * 64 + gxb) : 0);
        const float2* ppb = pr + (vb ? (gyb * 64 + gxb) : 0);

        uint32_t sbase = (uint32_t)__cvta_generic_to_shared(&S4[0]);
        uint32_t off0b = sbase + (uint32_t)(r0 * HX4 + c0) * 16;
        uint32_t off1b = sbase + (uint32_t)(r1 * HX4 + c1) * 16;

        // center pointers (output voxels always in-volume)
        const float2* ctrG = gt + (y0 + ly) * 64 + (x2_0 + lx);
        const float2* ctrP = pr + (y0 + ly) * 64 + (x2_0 + lx);

        // prologue: slices 0,1 -> buffer 0
        {
            #pragma unroll
            for (int sl = 0; sl < 2; sl++) {
                int zz = zbase + sl;
                bool vz = (unsigned)zz < 128u;
                int zoff = vz ? zz * 8192 : 0;
                int bA = (vz & va) ? 8 : 0;
                uint32_t d0 = off0b + RAW4(0, sl) * 16;
                cp8(d0, pga + zoff, bA);
                cp8(d0 + 8, ppa + zoff, bA);
                int bB = (vz & vb) ? 8 : 0;
                uint32_t d1 = off1b + RAW4(0, sl) * 16;
                if (hasE1) {
                    cp8(d1, pgb + zoff, bB);
                    cp8(d1 + 8, ppb + zoff, bB);
                }
            }
            CP_COMMIT();
            CP_WAIT0();
        }
        __syncthreads();

        float4 ring[5];
        #pragma unroll
        for (int k = 0; k < 5; k++) ring[k] = make_float4(0.f, 0.f, 0.f, 0.f);
        float accC = 0.f, accG = 0.f, accP = 0.f;

        const float kinv = 1.f / 125.f;

        #pragma unroll
        for (int it = 0; it < 18; it++) {
            const int cur = it & 1, nxt = cur ^ 1;

            // issue cp.async prefetch for slices 2it+2, 2it+3 -> raw[nxt]
            if (it < 17) {
                #pragma unroll
                for (int sl = 0; sl < 2; sl++) {
                    int zz = zbase + 2 * it + 2 + sl;
                    bool vz = (unsigned)zz < 128u;
                    int zoff = vz ? zz * 8192 : 0;
                    int bA = (vz & va) ? 8 : 0;
                    uint32_t d0 = off0b + RAW4(nxt, sl) * 16;
                    cp8(d0, pga + zoff, bA);
                    cp8(d0 + 8, ppa + zoff, bA);
                    int bB = (vz & vb) ? 8 : 0;
                    uint32_t d1 = off1b + RAW4(nxt, sl) * 16;
                    if (hasE1) {
                        cp8(d1, pgb + zoff, bB);
                        cp8(d1 + 8, ppb + zoff, bB);
                    }
                }
                CP_COMMIT();
            }

            // ---- x-pass for both slices of this pair
            #pragma unroll
            for (int sl = 0; sl < 2; sl++) {
                const float4* rp = &S4[RAW4(cur, sl)];
                float4* xp = &S4[XS4(cur, sl)];
                {
                    const float4* row = rp + ly * HX4;
                    float4 a = row[lx], b = row[lx + 1], c = row[lx + 2];
                    float tg = a.y + b.x + b.y + c.x;
                    float tp = a.w + b.z + b.w + c.z;
                    xp[ly * 32 + lx] = make_float4(a.x + tg, tg + c.y, a.z + tp, tp + c.w);
                }
                if (tid < 128) {
                    const float4* row = rp + (8 + ly) * HX4;
                    float4 a = row[lx], b = row[lx + 1], c = row[lx + 2];
                    float tg = a.y + b.x + b.y + c.x;
                    float tp = a.w + b.z + b.w + c.z;
                    xp[(8 + ly) * 32 + lx] = make_float4(a.x + tg, tg + c.y, a.z + tp, tp + c.w);
                }
            }

            CP_WAIT0();
            __syncthreads();

            // ---- y-pass + ring + combine, slice A (s = 2it)
            {
                const float4* xp = &S4[XS4(cur, 0)];
                float4 w0 = xp[(ly + 0) * 32 + lx];
                float4 w1 = xp[(ly + 1) * 32 + lx];
                float4 w2 = xp[(ly + 2) * 32 + lx];
                float4 w3 = xp[(ly + 3) * 32 + lx];
                float4 w4 = xp[(ly + 4) * 32 + lx];
                ring[(2 * it) % 5] = make_float4(w0.x + w1.x + w2.x + w3.x + w4.x,
                                                 w0.y + w1.y + w2.y + w3.y + w4.y,
                                                 w0.z + w1.z + w2.z + w3.z + w4.z,
                                                 w0.w + w1.w + w2.w + w3.w + w4.w);
            }
            if (it >= 2) {
                float4 S = make_float4(ring[0].x + ring[1].x + ring[2].x + ring[3].x + ring[4].x,
                                       ring[0].y + ring[1].y + ring[2].y + ring[3].y + ring[4].y,
                                       ring[0].z + ring[1].z + ring[2].z + ring[3].z + ring[4].z,
                                       ring[0].w + ring[1].w + ring[2].w + ring[3].w + ring[4].w);
                int zo = (zbase + 2 * it - 2) * 8192;
                float2 CG = __ldg(ctrG + zo);
                float2 CPv = __ldg(ctrP + zo);
                float dg0 = CG.x - S.x * kinv;
                float dg1 = CG.y - S.y * kinv;
                float dp0 = CPv.x - S.z * kinv;
                float dp1 = CPv.y - S.w * kinv;
                accG += dg0 * dg0 + dg1 * dg1;
                accP += dp0 * dp0 + dp1 * dp1;
                accC += dg0 * dp0 + dg1 * dp1;
            }

            // ---- y-pass + ring + combine, slice B (s = 2it+1)
            {
                const float4* xp = &S4[XS4(cur, 1)];
                float4 w0 = xp[(ly + 0) * 32 + lx];
                float4 w1 = xp[(ly + 1) * 32 + lx];
                float4 w2 = xp[(ly + 2) * 32 + lx];
                float4 w3 = xp[(ly + 3) * 32 + lx];
                float4 w4 = xp[(ly + 4) * 32 + lx];
                ring[(2 * it + 1) % 5] = make_float4(w0.x + w1.x + w2.x + w3.x + w4.x,
                                                     w0.y + w1.y + w2.y + w3.y + w4.y,
                                                     w0.z + w1.z + w2.z + w3.z + w4.z,
                                                     w0.w + w1.w + w2.w + w3.w + w4.w);
            }
            if (it >= 2) {
                float4 S = make_float4(ring[0].x + ring[1].x + ring[2].x + ring[3].x + ring[4].x,
                                       ring[0].y + ring[1].y + ring[2].y + ring[3].y + ring[4].y,
                                       ring[0].z + ring[1].z + ring[2].z + ring[3].z + ring[4].z,
                                       ring[0].w + ring[1].w + ring[2].w + ring[3].w + ring[4].w);
                int zo = (zbase + 2 * it - 1) * 8192;
                float2 CG = __ldg(ctrG + zo);
                float2 CPv = __ldg(ctrP + zo);
                float dg0 = CG.x - S.x * kinv;
                float dg1 = CG.y - S.y * kinv;
                float dp0 = CPv.x - S.z * kinv;
                float dp1 = CPv.y - S.w * kinv;
                accG += dg0 * dg0 + dg1 * dg1;
                accP += dp0 * dp0 + dp1 * dp1;
                accC += dg0 * dp0 + dg1 * dp1;
            }
        }

        float* scr = (float*)&S4[0];
        float c = warp_sum(accC);
        float gg = warp_sum(accG);
        float pp = warp_sum(accP);
        int wid = tid >> 5, lane = tid & 31;
        __syncthreads();
        if (lane == 0) { scr[wid] = c; scr[8 + wid] = gg; scr[16 + wid] = pp; }
        __syncthreads();
        if (tid == 0) {
            float C = 0, G = 0, P = 0;
            #pragma unroll
            for (int w = 0; w < 8; w++) { C += scr[w]; G += scr[8 + w]; P += scr[16 + w]; }
            int base = 1 + pair * 3;
            atomicAdd(&g_acc[base + 0], (double)C);
            atomicAdd(&g_acc[base + 1], (double)G);
            atomicAdd(&g_acc[base + 2], (double)P);
        }
    } else if (blkid < LCC_BLOCKS + REG_BLOCKS) {
        // ================= reg_field: sum((a-b)^2) =================
        const float4* a = (const float4*)F0;
        const float4* b = (const float4*)F0g;
        const int n4 = (2 * 3 * VOL) / 4;
        int bid = blkid - LCC_BLOCKS;
        float acc = 0.f;
        for (int i = bid * 256 + tid; i < n4; i += REG_BLOCKS * 256) {
            float4 x = a[i], y = b[i];
            float d0 = x.x - y.x, d1 = x.y - y.y, d2 = x.z - y.z, d3 = x.w - y.w;
            acc += d0 * d0 + d1 * d1 + d2 * d2 + d3 * d3;
        }
        float* scr = (float*)&S4[0];
        float w = warp_sum(acc);
        if ((tid & 31) == 0) scr[tid >> 5] = w;
        __syncthreads();
        if (tid == 0) {
            float v = 0.f;
            #pragma unroll
            for (int k = 0; k < 8; k++) v += scr[k];
            atomicAdd(&g_acc[0], (double)v);
        }
    } else {
        // ================= tversky: both pairs =================
        const float4* g0 = (const float4*)S0;
        const float4* p0 = (const float4*)S0g;
        const float4* g1 = (const float4*)S1;
        const float4* p1 = (const float4*)S1g;
        const int n4 = (2 * VOL) / 4;
        int bid = blkid - LCC_BLOCKS - REG_BLOCKS;
        float pr0 = 0.f, sm0 = 0.f, pr1 = 0.f, sm1 = 0.f;
        for (int i = bid * 256 + tid; i < n4; i += TV_BLOCKS * 256) {
            float4 a = g0[i], b = p0[i];
            pr0 += a.x * b.x + a.y * b.y + a.z * b.z + a.w * b.w;
            sm0 += a.x + b.x + a.y + b.y + a.z + b.z + a.w + b.w;
            float4 cc = g1[i], dd = p1[i];
            pr1 += cc.x * dd.x + cc.y * dd.y + cc.z * dd.z + cc.w * dd.w;
            sm1 += cc.x + dd.x + cc.y + dd.y + cc.z + dd.z + cc.w + dd.w;
        }
        float* scr = (float*)&S4[0];
        float v0 = warp_sum(pr0), v1 = warp_sum(sm0), v2 = warp_sum(pr1), v3 = warp_sum(sm1);
        int wid = tid >> 5;
        if ((tid & 31) == 0) { scr[wid] = v0; scr[8 + wid] = v1; scr[16 + wid] = v2; scr[24 + wid] = v3; }
        __syncthreads();
        if (tid == 0) {
            float t0 = 0, t1 = 0, t2 = 0, t3 = 0;
            #pragma unroll
            for (int k = 0; k < 8; k++) { t0 += scr[k]; t1 += scr[8 + k]; t2 += scr[16 + k]; t3 += scr[24 + k]; }
            atomicAdd(&g_acc[7], (double)t0);
            atomicAdd(&g_acc[8], (double)t1);
            atomicAdd(&g_acc[9], (double)t2);
            atomicAdd(&g_acc[10], (double)t3);
        }
    }

    // ---- last-block-done finalize ----
    if (tid == 0) {
        __threadfence();
        unsigned t = atomicAdd(&g_ticket, 1u);
        if (t == TOTAL_BLOCKS - 1) {
            __threadfence();
            volatile double* acc = g_acc;

            const double omega_f = 2.0 * 3.0 * VOL;
            const double omega_i = 2.0 * 1.0 * VOL;

            double rf = sqrt(acc[0]) / omega_f;

            double num0 = acc[1] * acc[1];
            double den0 = acc[2] * acc[3];
            den0 = den0 > 1e-5 ? den0 : 1e-5;
            double lcc0 = -(num0 / den0) / omega_i;

            double num1 = acc[4] * acc[4];
            double den1 = acc[5] * acc[6];
            den1 = den1 > 1e-5 ? den1 : 1e-5;
            double lcc1 = -(num1 / den1) / omega_i;

            double s0 = acc[8] > 1e-5 ? acc[8] : 1e-5;
            double s1 = acc[10] > 1e-5 ? acc[10] : 1e-5;
            double tv0 = -acc[7] / s0;
            double tv1 = -acc[9] / s1;

            out[0] = (float)(rf + 10.0 * (lcc0 + lcc1) + 10.0 * (tv0 + tv1));

            #pragma unroll
            for (int k = 0; k < 12; k++) g_acc[k] = 0.0;
            __threadfence();
            g_ticket = 0u;
        }
    }
}

extern "C" void kernel_launch(void* const* d_in, const int* in_sizes, int n_in,
                              void* d_out, int out_size) {
    const float* F0  = (const float*)d_in[0];
    const float* F0g = (const float*)d_in[1];
    const float* I0  = (const float*)d_in[2];
    const float* I0R = (const float*)d_in[3];
    const float* I1  = (const float*)d_in[4];
    const float* I1R = (const float*)d_in[5];
    const float* S0  = (const float*)d_in[6];
    const float* S0g = (const float*)d_in[7];
    const float* S1  = (const float*)d_in[8];
    const float* S1g = (const float*)d_in[9];
    float* out = (float*)d_out;

    cudaFuncSetAttribute(fused_kernel, cudaFuncAttributeMaxDynamicSharedMemorySize,
                         SMEM_BYTES);
    fused_kernel<<<TOTAL_BLOCKS, 256, SMEM_BYTES>>>(F0, F0g, I0, I0R, I1, I1R,
                                                    S0, S0g, S1, S1g, out);
}

// round 15
// speedup vs baseline: 1.3592x; 1.3592x over previous
#include <cuda_runtime.h>
#include <math.h>

#define VOL (128*128*128)

// Accumulators (double): 0 reg_sumsq | 1-3 pair0 cross/gg/pp | 4-6 pair1 | 7-8 tv0 prod/sum | 9-10 tv1
// Zero at load; last-finishing block emits result and re-zeroes for next replay.
__device__ double g_acc[12];
__device__ unsigned g_ticket;

__device__ __forceinline__ float warp_sum(float v) {
    #pragma unroll
    for (int o = 16; o > 0; o >>= 1) v += __shfl_xor_sync(0xffffffffu, v, o);
    return v;
}

// ---------------------------------------------------------------------------
// LCC geometry: tile 64(x) x 8(y) x 32(z), halo 2. NO raw SMEM stage:
// x-window sums are computed straight from coalesced global float2 loads in
// registers (cols gc2-1, gc2, gc2+1; overlaps are same-warp L1 hits), then
// stored packed {sg0,sg1,sp0,sp1} into a double-buffered xs plane. y-pass =
// 5 LDS.128; z-window in a float4 register ring; centers via __ldg (L2 hit).
// One barrier per slice. SMEM = 12.3KB/block.
// ---------------------------------------------------------------------------
#define TY 8
#define NSLICE 36

#define LCC_BLOCKS 512
#define REG_BLOCKS 512
#define TV_BLOCKS  256
#define TOTAL_BLOCKS (LCC_BLOCKS + REG_BLOCKS + TV_BLOCKS)

__global__ __launch_bounds__(256, 4) void fused_kernel(
    const float* __restrict__ F0, const float* __restrict__ F0g,
    const float* __restrict__ I0, const float* __restrict__ I0R,
    const float* __restrict__ I1, const float* __restrict__ I1R,
    const float* __restrict__ S0, const float* __restrict__ S0g,
    const float* __restrict__ S1, const float* __restrict__ S1g,
    float* __restrict__ out) {

    __shared__ float4 xs[2][12][32];   // {sg0,sg1,sp0,sp1}  12288 B

    int blkid = blockIdx.x;
    int tid = threadIdx.x;

    if (blkid < LCC_BLOCKS) {
        // ================= LCC =================
        int blk = blkid;
        int x2_0 = (blk & 1) * 32;            // tile x origin in float2 units
        int y0 = ((blk >> 1) & 15) * TY;
        int z0 = ((blk >> 5) & 3) * 32;
        int batch = (blk >> 7) & 1;
        int pair = blk >> 8;

        const float2* gt = (const float2*)((pair == 0 ? I0 : I1) + (size_t)batch * VOL);
        const float2* pr = (const float2*)((pair == 0 ? I0R : I1R) + (size_t)batch * VOL);

        int lx = tid & 31, ly = tid >> 5;
        int gc2 = x2_0 + lx;                  // global float2 column, 0..63
        bool vl = (gc2 >= 1), vr = (gc2 <= 62);
        int zbase = z0 - 2;

        // role 0: xs row r0 = ly+2 (rows 2..9); role 1 (tid<128): rows 0,1,10,11
        int r0 = ly + 2;
        int gy0 = y0 + ly;                    // always in [0,127]
        const float2* pG0 = gt + gy0 * 64 + gc2;
        const float2* pP0 = pr + gy0 * 64 + gc2;

        bool hasR1 = (tid < 128);
        int sel = tid >> 5;                   // 0..3 for tid<128
        int r1 = (sel < 2) ? sel : sel + 8;   // rows 0,1,10,11
        int gy1 = y0 + r1 - 2;                // may be out of [0,127]
        bool vrow1 = hasR1 & ((unsigned)gy1 < 128u);
        const float2* pG1 = gt + (vrow1 ? gy1 * 64 + gc2 : gc2);
        const float2* pP1 = pr + (vrow1 ? gy1 * 64 + gc2 : gc2);

        // center pointers (output voxels always in-volume)
        const float2* ctrG = pG0;
        const float2* ctrP = pP0;

        float4 ring[5];
        #pragma unroll
        for (int k = 0; k < 5; k++) ring[k] = make_float4(0.f, 0.f, 0.f, 0.f);
        float accC = 0.f, accG = 0.f, accP = 0.f;
        const float kinv = 1.f / 125.f;
        const float2 z2 = make_float2(0.f, 0.f);

        #pragma unroll
        for (int zi = 0; zi < NSLICE; zi++) {
            const int cur = zi & 1;
            int zz = zbase + zi;
            bool vz = (unsigned)zz < 128u;
            int zo = vz ? zz * 8192 : 0;

            // ---- x-pass role 0 (row r0): 6 predicated LDG.64 -> xs
            {
                float2 gb = vz ? __ldg(pG0 + zo) : z2;
                float2 ga = (vz & vl) ? __ldg(pG0 + zo - 1) : z2;
                float2 gc = (vz & vr) ? __ldg(pG0 + zo + 1) : z2;
                float2 pb = vz ? __ldg(pP0 + zo) : z2;
                float2 pa = (vz & vl) ? __ldg(pP0 + zo - 1) : z2;
                float2 pc = (vz & vr) ? __ldg(pP0 + zo + 1) : z2;
                float tg = ga.y + gb.x + gb.y + gc.x;
                float tp = pa.y + pb.x + pb.y + pc.x;
                xs[cur][r0][lx] = make_float4(ga.x + tg, tg + gc.y, pa.x + tp, tp + pc.y);
            }
            // ---- x-pass role 1 (halo rows 0,1,10,11)
            if (hasR1) {
                bool v1 = vrow1 & vz;
                float2 gb = v1 ? __ldg(pG1 + zo) : z2;
                float2 ga = (v1 & vl) ? __ldg(pG1 + zo - 1) : z2;
                float2 gc = (v1 & vr) ? __ldg(pG1 + zo + 1) : z2;
                float2 pb = v1 ? __ldg(pP1 + zo) : z2;
                float2 pa = (v1 & vl) ? __ldg(pP1 + zo - 1) : z2;
                float2 pc = (v1 & vr) ? __ldg(pP1 + zo + 1) : z2;
                float tg = ga.y + gb.x + gb.y + gc.x;
                float tp = pa.y + pb.x + pb.y + pc.x;
                xs[cur][r1][lx] = make_float4(ga.x + tg, tg + gc.y, pa.x + tp, tp + pc.y);
            }
            __syncthreads();

            // ---- y-pass: 5-row window; z held in float4 register ring
            {
                float4 w0 = xs[cur][ly + 0][lx];
                float4 w1 = xs[cur][ly + 1][lx];
                float4 w2 = xs[cur][ly + 2][lx];
                float4 w3 = xs[cur][ly + 3][lx];
                float4 w4 = xs[cur][ly + 4][lx];
                ring[zi % 5] = make_float4(w0.x + w1.x + w2.x + w3.x + w4.x,
                                           w0.y + w1.y + w2.y + w3.y + w4.y,
                                           w0.z + w1.z + w2.z + w3.z + w4.z,
                                           w0.w + w1.w + w2.w + w3.w + w4.w);
            }

            if (zi >= 4) {
                float4 S = make_float4(ring[0].x + ring[1].x + ring[2].x + ring[3].x + ring[4].x,
                                       ring[0].y + ring[1].y + ring[2].y + ring[3].y + ring[4].y,
                                       ring[0].z + ring[1].z + ring[2].z + ring[3].z + ring[4].z,
                                       ring[0].w + ring[1].w + ring[2].w + ring[3].w + ring[4].w);
                int zoc = (zbase + zi - 2) * 8192;
                float2 CG = __ldg(ctrG + zoc);
                float2 CP = __ldg(ctrP + zoc);
                float dg0 = CG.x - S.x * kinv;
                float dg1 = CG.y - S.y * kinv;
                float dp0 = CP.x - S.z * kinv;
                float dp1 = CP.y - S.w * kinv;
                accG += dg0 * dg0 + dg1 * dg1;
                accP += dp0 * dp0 + dp1 * dp1;
                accC += dg0 * dp0 + dg1 * dp1;
            }
        }

        float* scr = (float*)&xs[0][0][0];
        float c = warp_sum(accC);
        float gg = warp_sum(accG);
        float pp = warp_sum(accP);
        int wid = tid >> 5, lane = tid & 31;
        __syncthreads();
        if (lane == 0) { scr[wid] = c; scr[8 + wid] = gg; scr[16 + wid] = pp; }
        __syncthreads();
        if (tid == 0) {
            float C = 0, G = 0, P = 0;
            #pragma unroll
            for (int w = 0; w < 8; w++) { C += scr[w]; G += scr[8 + w]; P += scr[16 + w]; }
            int base = 1 + pair * 3;
            atomicAdd(&g_acc[base + 0], (double)C);
            atomicAdd(&g_acc[base + 1], (double)G);
            atomicAdd(&g_acc[base + 2], (double)P);
        }
    } else if (blkid < LCC_BLOCKS + REG_BLOCKS) {
        // ================= reg_field: sum((a-b)^2) =================
        const float4* a = (const float4*)F0;
        const float4* b = (const float4*)F0g;
        const int n4 = (2 * 3 * VOL) / 4;
        int bid = blkid - LCC_BLOCKS;
        float acc = 0.f;
        for (int i = bid * 256 + tid; i < n4; i += REG_BLOCKS * 256) {
            float4 x = a[i], y = b[i];
            float d0 = x.x - y.x, d1 = x.y - y.y, d2 = x.z - y.z, d3 = x.w - y.w;
            acc += d0 * d0 + d1 * d1 + d2 * d2 + d3 * d3;
        }
        float* scr = (float*)&xs[0][0][0];
        float w = warp_sum(acc);
        if ((tid & 31) == 0) scr[tid >> 5] = w;
        __syncthreads();
        if (tid == 0) {
            float v = 0.f;
            #pragma unroll
            for (int k = 0; k < 8; k++) v += scr[k];
            atomicAdd(&g_acc[0], (double)v);
        }
    } else {
        // ================= tversky: both pairs =================
        const float4* g0 = (const float4*)S0;
        const float4* p0 = (const float4*)S0g;
        const float4* g1 = (const float4*)S1;
        const float4* p1 = (const float4*)S1g;
        const int n4 = (2 * VOL) / 4;
        int bid = blkid - LCC_BLOCKS - REG_BLOCKS;
        float pr0 = 0.f, sm0 = 0.f, pr1 = 0.f, sm1 = 0.f;
        for (int i = bid * 256 + tid; i < n4; i += TV_BLOCKS * 256) {
            float4 a = g0[i], b = p0[i];
            pr0 += a.x * b.x + a.y * b.y + a.z * b.z + a.w * b.w;
            sm0 += a.x + b.x + a.y + b.y + a.z + b.z + a.w + b.w;
            float4 cc = g1[i], dd = p1[i];
            pr1 += cc.x * dd.x + cc.y * dd.y + cc.z * dd.z + cc.w * dd.w;
            sm1 += cc.x + dd.x + cc.y + dd.y + cc.z + dd.z + cc.w + dd.w;
        }
        float* scr = (float*)&xs[0][0][0];
        float v0 = warp_sum(pr0), v1 = warp_sum(sm0), v2 = warp_sum(pr1), v3 = warp_sum(sm1);
        int wid = tid >> 5;
        if ((tid & 31) == 0) { scr[wid] = v0; scr[8 + wid] = v1; scr[16 + wid] = v2; scr[24 + wid] = v3; }
        __syncthreads();
        if (tid == 0) {
            float t0 = 0, t1 = 0, t2 = 0, t3 = 0;
            #pragma unroll
            for (int k = 0; k < 8; k++) { t0 += scr[k]; t1 += scr[8 + k]; t2 += scr[16 + k]; t3 += scr[24 + k]; }
            atomicAdd(&g_acc[7], (double)t0);
            atomicAdd(&g_acc[8], (double)t1);
            atomicAdd(&g_acc[9], (double)t2);
            atomicAdd(&g_acc[10], (double)t3);
        }
    }

    // ---- last-block-done finalize ----
    if (tid == 0) {
        __threadfence();
        unsigned t = atomicAdd(&g_ticket, 1u);
        if (t == TOTAL_BLOCKS - 1) {
            __threadfence();
            volatile double* acc = g_acc;

            const double omega_f = 2.0 * 3.0 * VOL;
            const double omega_i = 2.0 * 1.0 * VOL;

            double rf = sqrt(acc[0]) / omega_f;

            double num0 = acc[1] * acc[1];
            double den0 = acc[2] * acc[3];
            den0 = den0 > 1e-5 ? den0 : 1e-5;
            double lcc0 = -(num0 / den0) / omega_i;

            double num1 = acc[4] * acc[4];
            double den1 = acc[5] * acc[6];
            den1 = den1 > 1e-5 ? den1 : 1e-5;
            double lcc1 = -(num1 / den1) / omega_i;

            double s0 = acc[8] > 1e-5 ? acc[8] : 1e-5;
            double s1 = acc[10] > 1e-5 ? acc[10] : 1e-5;
            double tv0 = -acc[7] / s0;
            double tv1 = -acc[9] / s1;

            out[0] = (float)(rf + 10.0 * (lcc0 + lcc1) + 10.0 * (tv0 + tv1));

            #pragma unroll
            for (int k = 0; k < 12; k++) g_acc[k] = 0.0;
            __threadfence();
            g_ticket = 0u;
        }
    }
}

extern "C" void kernel_launch(void* const* d_in, const int* in_sizes, int n_in,
                              void* d_out, int out_size) {
    const float* F0  = (const float*)d_in[0];
    const float* F0g = (const float*)d_in[1];
    const float* I0  = (const float*)d_in[2];
    const float* I0R = (const float*)d_in[3];
    const float* I1  = (const float*)d_in[4];
    const float* I1R = (const float*)d_in[5];
    const float* S0  = (const float*)d_in[6];
    const float* S0g = (const float*)d_in[7];
    const float* S1  = (const float*)d_in[8];
    const float* S1g = (const float*)d_in[9];
    float* out = (float*)d_out;

    fused_kernel<<<TOTAL_BLOCKS, 256>>>(F0, F0g, I0, I0R, I1, I1R,
                                        S0, S0g, S1, S1g, out);
}